// round 7
// baseline (speedup 1.0000x reference)
#include <cuda_runtime.h>
#include <cuda_fp16.h>

#define N       4096
#define NB      128     // persistent blocks, 1/SM, co-resident wave 1
#define NT      1024
#define RPB     32      // rows per block
#define NIT8    26      // fp8 (e4m3) iterations  (proven accuracy @ 26+6)
#define NIT16   6       // fp16 refinement iterations
#define NCTR    8       // sharded barrier counters
#define CPC     (NB / NCTR)   // CTAs per counter = 16

// dynamic SMEM layout
#define SM_STRIP   (RPB * N)                 // 131072 B : K^T strip, e4m3
#define SM_VEC     (N * 4)                   // 16384 B  : fp32 vector
#define SM_VH      (N * 2)                   // 8192 B   : fp16 vector
#define SM_PART    (RPB * 4 * 4)             // 512 B
#define SM_AF      (RPB * 4)                 // 128 B
#define SMEM_DYN   (SM_STRIP + SM_VEC + SM_VH + SM_PART + SM_AF)

// ---- persistent device scratch ----
__device__ __align__(16) __half        g_Kh [(size_t)N * N];   // K fp16 row-major (32 MB)
__device__ __align__(16) __half        g_KhT[(size_t)N * N];   // K^T fp16         (32 MB)
__device__ __align__(16) unsigned char g_K8 [(size_t)N * N];   // K e4m3           (16 MB)
__device__ __align__(16) float g_AF[N];
__device__ __align__(16) float g_BF[N];
__device__ __align__(16) unsigned g_bar[NCTR * 64];            // 8 counters, 256B apart

__global__ void reset_bar_kernel() { g_bar[threadIdx.x * 64] = 0u; }

// ---- sharded grid barrier: proven red.release arrival (R3/R4 path), 8-way
//      address sharding to kill L2 atomic-ALU serialization. No gpu fence =>
//      no CCTL.IVALL on the hot path. Correctness: counter c reaches 16n only
//      after all its 16 CTAs arrived n times, and no CTA arrives at n+1 before
//      ALL counters hit 16n (its own poll gates it). ----
__device__ __forceinline__ void grid_sync(unsigned target_per_ctr, int bid) {
    __syncthreads();
    if (threadIdx.x == 0) {
        asm volatile("red.release.gpu.global.add.u32 [%0], %1;"
                     :: "l"(&g_bar[(bid & (NCTR - 1)) * 64]), "r"(1u) : "memory");
        while (true) {
            unsigned v[NCTR];
#pragma unroll
            for (int c = 0; c < NCTR; ++c)
                asm volatile("ld.global.cg.u32 %0, [%1];"
                             : "=r"(v[c]) : "l"(&g_bar[c * 64]) : "memory");
            bool ok = true;
#pragma unroll
            for (int c = 0; c < NCTR; ++c) ok &= (v[c] >= target_per_ctr);
            if (ok) break;
        }
    }
    __syncthreads();
}

// ---- fp8 helpers ----
__device__ __forceinline__ unsigned h2_to_e4m3x2(unsigned h2bits) {
    unsigned short r;
    asm("cvt.rn.satfinite.e4m3x2.f16x2 %0, %1;" : "=h"(r) : "r"(h2bits));
    return (unsigned)r;
}
__device__ __forceinline__ __half2 e4m3x2_to_h2(unsigned short u) {
    unsigned r;
    asm("cvt.rn.f16x2.e4m3x2 %0, %1;" : "=r"(r) : "h"(u));
    return *reinterpret_cast<__half2*>(&r);
}

__device__ __forceinline__ void load_vec_f(float* s_vec, const float* g_src, int tid) {
    ((float4*)s_vec)[tid] = __ldcg((const float4*)g_src + tid);
}
__device__ __forceinline__ void load_vec_h(__half2* s_vh, const float* g_src, int tid) {
    float4 v = __ldcg((const float4*)g_src + tid);
    s_vh[2 * tid]     = __floats2half2_rn(v.x, v.y);
    s_vh[2 * tid + 1] = __floats2half2_rn(v.z, v.w);
}

// core fp8 dot on 4 rows x 1024 cols given a row base pointer with stride N
__device__ __forceinline__ void dot8_body(const unsigned char* __restrict__ Mp, bool glob,
                                          const uint4* __restrict__ vh4, int lane,
                                          float acc[4])
{
#pragma unroll
    for (int s = 0; s < 2; ++s) {
        const int e0 = (s << 9) + (lane << 4);               // 16 fp8 per lane per step
        uint4 va = vh4[(e0 >> 3)];
        uint4 vb = vh4[(e0 >> 3) + 1];
        const __half2* vha = (const __half2*)&va;
        const __half2* vhb = (const __half2*)&vb;
#pragma unroll
        for (int r = 0; r < 4; ++r) {
            const uint4* p = (const uint4*)(Mp + (size_t)r * N + e0);
            uint4 kd = glob ? __ldcg(p) : *p;                // LDS when SMEM provenance
            __half2 a2 = __floats2half2_rn(0.f, 0.f);
            a2 = __hfma2(e4m3x2_to_h2((unsigned short)kd.x),         vha[0], a2);
            a2 = __hfma2(e4m3x2_to_h2((unsigned short)(kd.x >> 16)), vha[1], a2);
            a2 = __hfma2(e4m3x2_to_h2((unsigned short)kd.y),         vha[2], a2);
            a2 = __hfma2(e4m3x2_to_h2((unsigned short)(kd.y >> 16)), vha[3], a2);
            a2 = __hfma2(e4m3x2_to_h2((unsigned short)kd.z),         vhb[0], a2);
            a2 = __hfma2(e4m3x2_to_h2((unsigned short)(kd.z >> 16)), vhb[1], a2);
            a2 = __hfma2(e4m3x2_to_h2((unsigned short)kd.w),         vhb[2], a2);
            a2 = __hfma2(e4m3x2_to_h2((unsigned short)(kd.w >> 16)), vhb[3], a2);
            float2 f = __half22float2(a2);
            acc[r] += f.x + f.y;
        }
    }
}

__device__ __forceinline__ void warp_reduce_part(float acc[4], int r0, int q, int lane,
                                                 float* __restrict__ s_part)
{
#pragma unroll
    for (int r = 0; r < 4; ++r) {
        float a = acc[r];
#pragma unroll
        for (int off = 16; off; off >>= 1) a += __shfl_xor_sync(0xffffffffu, a, off);
        if (lane == 0) s_part[((r0 + r) << 2) + q] = a;
    }
}

// fp16 strip dot (fp32 vector + fp32 accum), rows from L2
__device__ __forceinline__ void dot16(const __half* __restrict__ M,
                                      const float*  __restrict__ s_vec,
                                      int i0, int g, int q, int lane,
                                      float* __restrict__ s_part)
{
    const int c0 = q << 10;
    const int r0 = g << 2;
    const __half* Mp = M + (size_t)(i0 + r0) * N + c0;
    const float4* sv4 = (const float4*)(s_vec + c0);

    float acc[4] = {0.f, 0.f, 0.f, 0.f};
#pragma unroll
    for (int s = 0; s < 4; ++s) {
        const int i = (s << 8) + (lane << 3);
        const float4 v0 = sv4[(i >> 2)];
        const float4 v1 = sv4[(i >> 2) + 1];
#pragma unroll
        for (int r = 0; r < 4; ++r) {
            const float4 kr = __ldcg((const float4*)(Mp + (size_t)r * N + i));
            const __half2* h = (const __half2*)&kr;
            const float2 f0 = __half22float2(h[0]);
            const float2 f1 = __half22float2(h[1]);
            const float2 f2 = __half22float2(h[2]);
            const float2 f3 = __half22float2(h[3]);
            acc[r] += f0.x * v0.x + f0.y * v0.y + f1.x * v0.z + f1.y * v0.w
                    + f2.x * v1.x + f2.y * v1.y + f3.x * v1.z + f3.y * v1.w;
        }
    }
    warp_reduce_part(acc, r0, q, lane, s_part);
}

__global__ void __launch_bounds__(NT, 1)
competitive_kernel(const float* __restrict__ AT, const float* __restrict__ k,
                   const float* __restrict__ bt, float* __restrict__ C)
{
    extern __shared__ char s_dyn[];
    unsigned char* s_strip = (unsigned char*)s_dyn;                    // 128 KB K^T fp8 strip
    float*   s_vec  = (float*)  (s_dyn + SM_STRIP);                    // 16 KB
    __half2* s_vh   = (__half2*)(s_dyn + SM_STRIP + SM_VEC);           // 8 KB
    float*   s_part = (float*)  (s_dyn + SM_STRIP + SM_VEC + SM_VH);
    float*   s_af   = (float*)  (s_dyn + SM_STRIP + SM_VEC + SM_VH + SM_PART);

    const int tid  = threadIdx.x;
    const int w    = tid >> 5;
    const int lane = tid & 31;
    const int g    = w >> 2;                 // row group 0..7
    const int q    = w & 3;                  // column quarter 0..3
    const int bid  = blockIdx.x;
    const int i0   = bid * RPB;

    float r_at = 0.f, r_bt2 = 0.f;
    if (tid < RPB) {
        r_at = AT[i0 + tid];
        float b = bt[i0 + tid];
        r_bt2 = b * b;
    }

    // ---------- setup (fused): Kh = fp16(k*k), K8 = fp8(k*k), KhT = transpose ----------
    {
        float (*s_tile)[33] = (float(*)[33])s_vec;      // 64*33*4 = 8.4 KB
        for (int t = 0; t < N / 64; ++t) {
            const int j0 = t * 64;
            const size_t roff = (size_t)(i0 + w) * N + j0;
            float2 v = __ldcs((const float2*)(k + roff) + lane);
            v.x *= v.x; v.y *= v.y;
            const __half2 h2 = __floats2half2_rn(v.x, v.y);
            *(__half2*)(g_Kh + roff + lane * 2) = h2;
            *(unsigned short*)(g_K8 + roff + lane * 2) =
                (unsigned short)h2_to_e4m3x2(*(const unsigned*)&h2);
            s_tile[lane * 2    ][w] = v.x;
            s_tile[lane * 2 + 1][w] = v.y;
            __syncthreads();
#pragma unroll
            for (int qq = 0; qq < 2; ++qq) {
                const int c = w * 2 + qq;
                g_KhT[(size_t)(j0 + c) * N + i0 + lane] = __float2half(s_tile[c][lane]);
            }
            __syncthreads();
        }
    }
    if (tid < RPB) __stcg(&g_AF[i0 + tid], r_at);

    unsigned tgt = 0;
    grid_sync(tgt += CPC, bid);

    // ---------- gather this block's K^T strip into SMEM as fp8 ----------
    {
        const uint4* src = (const uint4*)(g_KhT + (size_t)i0 * N);   // 32 rows x 4096 halfs
        uint2* dst = (uint2*)s_strip;
#pragma unroll 4
        for (int s = 0; s < 16; ++s) {
            const int idx = s * NT + tid;                 // 16384 uint4 chunks (8 halfs)
            uint4 h8 = __ldcg(src + idx);
            uint2 o;
            o.x = h2_to_e4m3x2(h8.x) | (h2_to_e4m3x2(h8.y) << 16);
            o.y = h2_to_e4m3x2(h8.z) | (h2_to_e4m3x2(h8.w) << 16);
            dst[idx] = o;
        }
    }
    __syncthreads();

    // ---------- fp8 iterations ----------
    for (int it = 0; it < NIT8; ++it) {
        // BF = bt^2 / (1 + K^T @ AF)  -- strip from SMEM, zero global loads
        load_vec_h(s_vh, g_AF, tid);
        __syncthreads();
        {
            float acc[4] = {0.f, 0.f, 0.f, 0.f};
            const unsigned char* Mp = s_strip + (size_t)(g << 2) * N + (q << 10);
            const uint4* vh4 = (const uint4*)((const char*)s_vh + (q << 11));
            dot8_body(Mp, false, vh4, lane, acc);
            warp_reduce_part(acc, g << 2, q, lane, s_part);
        }
        __syncthreads();
        if (tid < RPB) {
            const float a = s_part[tid * 4] + s_part[tid * 4 + 1]
                          + s_part[tid * 4 + 2] + s_part[tid * 4 + 3];
            __stcg(&g_BF[i0 + tid], r_bt2 / (1.0f + a));
        }
        grid_sync(tgt += CPC, bid);

        // AF = AT / (1 + K @ BF)  -- K strip from L2 (written by this SM, stays hot)
        load_vec_h(s_vh, g_BF, tid);
        __syncthreads();
        {
            float acc[4] = {0.f, 0.f, 0.f, 0.f};
            const unsigned char* Mp = g_K8 + (size_t)(i0 + (g << 2)) * N + (q << 10);
            const uint4* vh4 = (const uint4*)((const char*)s_vh + (q << 11));
            dot8_body(Mp, true, vh4, lane, acc);
            warp_reduce_part(acc, g << 2, q, lane, s_part);
        }
        __syncthreads();
        if (tid < RPB) {
            const float a = s_part[tid * 4] + s_part[tid * 4 + 1]
                          + s_part[tid * 4 + 2] + s_part[tid * 4 + 3];
            __stcg(&g_AF[i0 + tid], r_at / (1.0f + a));
        }
        grid_sync(tgt += CPC, bid);
    }

    // ---------- fp16 refinement iterations ----------
    for (int it = 0; it < NIT16; ++it) {
        load_vec_f(s_vec, g_AF, tid);
        __syncthreads();
        dot16(g_KhT, s_vec, i0, g, q, lane, s_part);
        __syncthreads();
        if (tid < RPB) {
            const float a = s_part[tid * 4] + s_part[tid * 4 + 1]
                          + s_part[tid * 4 + 2] + s_part[tid * 4 + 3];
            __stcg(&g_BF[i0 + tid], r_bt2 / (1.0f + a));
        }
        grid_sync(tgt += CPC, bid);

        load_vec_f(s_vec, g_BF, tid);
        __syncthreads();
        dot16(g_Kh, s_vec, i0, g, q, lane, s_part);
        __syncthreads();
        if (tid < RPB) {
            const float a = s_part[tid * 4] + s_part[tid * 4 + 1]
                          + s_part[tid * 4 + 2] + s_part[tid * 4 + 3];
            const float af = r_at / (1.0f + a);
            if (it == NIT16 - 1) s_af[tid] = af;           // final: keep local
            else                 __stcg(&g_AF[i0 + tid], af);
        }
        if (it != NIT16 - 1) grid_sync(tgt += CPC, bid);
        else                 __syncthreads();
    }

    // ---------- output: C[i][j] = AF_i * k_ij^2 * BF_j  (fp32 k) ----------
    load_vec_f(s_vec, g_BF, tid);
    __syncthreads();

    const float af = s_af[w];                              // warp w -> row i0 + w
    const float4* sv4 = (const float4*)s_vec;
#pragma unroll 4
    for (int s = 0; s < 32; ++s) {
        const int j = s * 128 + lane * 4;
        const size_t off = (size_t)(i0 + w) * N + j;
        const float4 kv = __ldcs((const float4*)(k + off));
        const float4 bv = sv4[j >> 2];
        float4 c4;
        c4.x = af * kv.x * kv.x * bv.x;
        c4.y = af * kv.y * kv.y * bv.y;
        c4.z = af * kv.z * kv.z * bv.z;
        c4.w = af * kv.w * kv.w * bv.w;
        *(float4*)(C + off) = c4;
    }
}

extern "C" void kernel_launch(void* const* d_in, const int* in_sizes, int n_in,
                              void* d_out, int out_size) {
    const float* AT = (const float*)d_in[0];
    const float* k  = (const float*)d_in[1];
    const float* bt = (const float*)d_in[2];
    float* C = (float*)d_out;

    cudaFuncSetAttribute(competitive_kernel,
                         cudaFuncAttributeMaxDynamicSharedMemorySize, SMEM_DYN);
    reset_bar_kernel<<<1, NCTR>>>();
    competitive_kernel<<<NB, NT, SMEM_DYN>>>(AT, k, bt, C);
}

// round 8
// speedup vs baseline: 1.0143x; 1.0143x over previous
#include <cuda_runtime.h>
#include <cuda_fp16.h>

#define N       4096
#define NB      128     // persistent blocks, 1/SM, co-resident wave 1
#define NT      1024
#define RPB     32      // rows per block
#define NIT8    26      // fp8 (e4m3) iterations  (proven accuracy @ 26+6)
#define NIT16   6       // fp16 refinement iterations
#define PREF_ROWS 16    // A-strip rows resident in SMEM (64 KB)

// dynamic SMEM layout
#define SM_STRIP   (RPB * N)                 // 131072 B : K^T strip, e4m3
#define SM_PREF    (PREF_ROWS * N)           // 65536 B  : first half of A-strip, e4m3
#define SM_VEC     (N * 4)                   // 16384 B  : fp32 vector
#define SM_VH      (N * 2)                   // 8192 B   : fp16 vector
#define SM_PART    (RPB * 4 * 4)             // 512 B
#define SM_AF      (RPB * 4)                 // 128 B
#define SMEM_DYN   (SM_STRIP + SM_PREF + SM_VEC + SM_VH + SM_PART + SM_AF)  // ~216.6 KB

// ---- persistent device scratch ----
__device__ __align__(16) __half        g_Kh [(size_t)N * N];   // K fp16 row-major (32 MB)
__device__ __align__(16) __half        g_KhT[(size_t)N * N];   // K^T fp16         (32 MB)
__device__ __align__(16) unsigned char g_K8 [(size_t)N * N];   // K e4m3           (16 MB)
__device__ __align__(16) float g_AF[N];
__device__ __align__(16) float g_BF[N];
__device__ unsigned int g_bar;

__global__ void reset_bar_kernel() { g_bar = 0u; }

// ---- proven grid barrier (R3/R4): red.release arrive + L2 poll, no gpu fence
//      on the hot path => no CCTL.IVALL => SMEM/L1 state survives. ----
__device__ __forceinline__ void grid_sync(unsigned target) {
    __syncthreads();
    if (threadIdx.x == 0) {
        asm volatile("red.release.gpu.global.add.u32 [%0], %1;"
                     :: "l"(&g_bar), "r"(1u) : "memory");
        unsigned v;
        do {
            asm volatile("ld.global.cg.u32 %0, [%1];" : "=r"(v) : "l"(&g_bar) : "memory");
        } while (v < target);
    }
    __syncthreads();
}

// ---- fp8 helpers ----
__device__ __forceinline__ unsigned h2_to_e4m3x2(unsigned h2bits) {
    unsigned short r;
    asm("cvt.rn.satfinite.e4m3x2.f16x2 %0, %1;" : "=h"(r) : "r"(h2bits));
    return (unsigned)r;
}
__device__ __forceinline__ __half2 e4m3x2_to_h2(unsigned short u) {
    unsigned r;
    asm("cvt.rn.f16x2.e4m3x2 %0, %1;" : "=r"(r) : "h"(u));
    return *reinterpret_cast<__half2*>(&r);
}

__device__ __forceinline__ void load_vec_f(float* s_vec, const float* g_src, int tid) {
    ((float4*)s_vec)[tid] = __ldcg((const float4*)g_src + tid);
}
__device__ __forceinline__ void load_vec_h(__half2* s_vh, const float* g_src, int tid) {
    float4 v = __ldcg((const float4*)g_src + tid);
    s_vh[2 * tid]     = __floats2half2_rn(v.x, v.y);
    s_vh[2 * tid + 1] = __floats2half2_rn(v.z, v.w);
}

// core fp8 dot on 4 rows x 1024 cols given a row base pointer with stride N
__device__ __forceinline__ void dot8_body(const unsigned char* __restrict__ Mp, bool glob,
                                          const uint4* __restrict__ vh4, int lane,
                                          float acc[4])
{
#pragma unroll
    for (int s = 0; s < 2; ++s) {
        const int e0 = (s << 9) + (lane << 4);               // 16 fp8 per lane per step
        uint4 va = vh4[(e0 >> 3)];
        uint4 vb = vh4[(e0 >> 3) + 1];
        const __half2* vha = (const __half2*)&va;
        const __half2* vhb = (const __half2*)&vb;
#pragma unroll
        for (int r = 0; r < 4; ++r) {
            const uint4* p = (const uint4*)(Mp + (size_t)r * N + e0);
            uint4 kd = glob ? __ldcg(p) : *p;                // LDS when SMEM provenance
            __half2 a2 = __floats2half2_rn(0.f, 0.f);
            a2 = __hfma2(e4m3x2_to_h2((unsigned short)kd.x),         vha[0], a2);
            a2 = __hfma2(e4m3x2_to_h2((unsigned short)(kd.x >> 16)), vha[1], a2);
            a2 = __hfma2(e4m3x2_to_h2((unsigned short)kd.y),         vha[2], a2);
            a2 = __hfma2(e4m3x2_to_h2((unsigned short)(kd.y >> 16)), vha[3], a2);
            a2 = __hfma2(e4m3x2_to_h2((unsigned short)kd.z),         vhb[0], a2);
            a2 = __hfma2(e4m3x2_to_h2((unsigned short)(kd.z >> 16)), vhb[1], a2);
            a2 = __hfma2(e4m3x2_to_h2((unsigned short)kd.w),         vhb[2], a2);
            a2 = __hfma2(e4m3x2_to_h2((unsigned short)(kd.w >> 16)), vhb[3], a2);
            float2 f = __half22float2(a2);
            acc[r] += f.x + f.y;
        }
    }
}

__device__ __forceinline__ void warp_reduce_part(float acc[4], int r0, int q, int lane,
                                                 float* __restrict__ s_part)
{
#pragma unroll
    for (int r = 0; r < 4; ++r) {
        float a = acc[r];
#pragma unroll
        for (int off = 16; off; off >>= 1) a += __shfl_xor_sync(0xffffffffu, a, off);
        if (lane == 0) s_part[((r0 + r) << 2) + q] = a;
    }
}

// fp16 strip dot (fp32 vector + fp32 accum), rows from L2
__device__ __forceinline__ void dot16(const __half* __restrict__ M,
                                      const float*  __restrict__ s_vec,
                                      int i0, int g, int q, int lane,
                                      float* __restrict__ s_part)
{
    const int c0 = q << 10;
    const int r0 = g << 2;
    const __half* Mp = M + (size_t)(i0 + r0) * N + c0;
    const float4* sv4 = (const float4*)(s_vec + c0);

    float acc[4] = {0.f, 0.f, 0.f, 0.f};
#pragma unroll
    for (int s = 0; s < 4; ++s) {
        const int i = (s << 8) + (lane << 3);
        const float4 v0 = sv4[(i >> 2)];
        const float4 v1 = sv4[(i >> 2) + 1];
#pragma unroll
        for (int r = 0; r < 4; ++r) {
            const float4 kr = __ldcg((const float4*)(Mp + (size_t)r * N + i));
            const __half2* h = (const __half2*)&kr;
            const float2 f0 = __half22float2(h[0]);
            const float2 f1 = __half22float2(h[1]);
            const float2 f2 = __half22float2(h[2]);
            const float2 f3 = __half22float2(h[3]);
            acc[r] += f0.x * v0.x + f0.y * v0.y + f1.x * v0.z + f1.y * v0.w
                    + f2.x * v1.x + f2.y * v1.y + f3.x * v1.z + f3.y * v1.w;
        }
    }
    warp_reduce_part(acc, r0, q, lane, s_part);
}

__global__ void __launch_bounds__(NT, 1)
competitive_kernel(const float* __restrict__ AT, const float* __restrict__ k,
                   const float* __restrict__ bt, float* __restrict__ C)
{
    extern __shared__ char s_dyn[];
    unsigned char* s_strip = (unsigned char*)s_dyn;                        // 128 KB K^T strip
    unsigned char* s_pref  = (unsigned char*)(s_dyn + SM_STRIP);           // 64 KB A-strip rows 0..15
    float*   s_vec  = (float*)  (s_dyn + SM_STRIP + SM_PREF);              // 16 KB
    __half2* s_vh   = (__half2*)(s_dyn + SM_STRIP + SM_PREF + SM_VEC);     // 8 KB
    float*   s_part = (float*)  (s_dyn + SM_STRIP + SM_PREF + SM_VEC + SM_VH);
    float*   s_af   = (float*)  (s_dyn + SM_STRIP + SM_PREF + SM_VEC + SM_VH + SM_PART);

    const int tid  = threadIdx.x;
    const int w    = tid >> 5;
    const int lane = tid & 31;
    const int g    = w >> 2;                 // row group 0..7
    const int q    = w & 3;                  // column quarter 0..3
    const int bid  = blockIdx.x;
    const int i0   = bid * RPB;

    float r_at = 0.f, r_bt2 = 0.f;
    if (tid < RPB) {
        r_at = AT[i0 + tid];
        float b = bt[i0 + tid];
        r_bt2 = b * b;
    }

    // ---------- setup (fused): Kh = fp16(k*k), K8 = fp8(k*k), KhT = transpose ----------
    {
        float (*s_tile)[33] = (float(*)[33])s_vec;      // 64*33*4 = 8.4 KB
        for (int t = 0; t < N / 64; ++t) {
            const int j0 = t * 64;
            const size_t roff = (size_t)(i0 + w) * N + j0;
            float2 v = __ldcs((const float2*)(k + roff) + lane);
            v.x *= v.x; v.y *= v.y;
            const __half2 h2 = __floats2half2_rn(v.x, v.y);
            *(__half2*)(g_Kh + roff + lane * 2) = h2;
            *(unsigned short*)(g_K8 + roff + lane * 2) =
                (unsigned short)h2_to_e4m3x2(*(const unsigned*)&h2);
            s_tile[lane * 2    ][w] = v.x;
            s_tile[lane * 2 + 1][w] = v.y;
            __syncthreads();
#pragma unroll
            for (int qq = 0; qq < 2; ++qq) {
                const int c = w * 2 + qq;
                g_KhT[(size_t)(j0 + c) * N + i0 + lane] = __float2half(s_tile[c][lane]);
            }
            __syncthreads();
        }
    }
    if (tid < RPB) __stcg(&g_AF[i0 + tid], r_at);

    unsigned tgt = 0;
    grid_sync(tgt += NB);

    // ---------- gather K^T strip into SMEM as fp8; copy A-strip rows 0..15 ----------
    {
        const uint4* src = (const uint4*)(g_KhT + (size_t)i0 * N);   // 32 rows x 4096 halfs
        uint2* dst = (uint2*)s_strip;
#pragma unroll 4
        for (int s = 0; s < 16; ++s) {
            const int idx = s * NT + tid;                 // 16384 uint4 chunks (8 halfs)
            uint4 h8 = __ldcg(src + idx);
            uint2 o;
            o.x = h2_to_e4m3x2(h8.x) | (h2_to_e4m3x2(h8.y) << 16);
            o.y = h2_to_e4m3x2(h8.z) | (h2_to_e4m3x2(h8.w) << 16);
            dst[idx] = o;
        }
        // half of this block's A-strip (g_K8 rows i0..i0+15) -> SMEM, bit-exact copy
        const uint4* asrc = (const uint4*)(g_K8 + (size_t)i0 * N);
        uint4* adst = (uint4*)s_pref;
#pragma unroll
        for (int s = 0; s < 4; ++s) {
            const int idx = s * NT + tid;                 // 4096 chunks of 16 B
            adst[idx] = __ldcg(asrc + idx);
        }
    }
    __syncthreads();

    // ---------- fp8 iterations ----------
    for (int it = 0; it < NIT8; ++it) {
        // BF = bt^2 / (1 + K^T @ AF)  -- strip from SMEM, zero global loads
        load_vec_h(s_vh, g_AF, tid);
        __syncthreads();
        {
            float acc[4] = {0.f, 0.f, 0.f, 0.f};
            const unsigned char* Mp = s_strip + (size_t)(g << 2) * N + (q << 10);
            const uint4* vh4 = (const uint4*)((const char*)s_vh + (q << 11));
            dot8_body(Mp, false, vh4, lane, acc);
            warp_reduce_part(acc, g << 2, q, lane, s_part);
        }
        __syncthreads();
        if (tid < RPB) {
            const float a = s_part[tid * 4] + s_part[tid * 4 + 1]
                          + s_part[tid * 4 + 2] + s_part[tid * 4 + 3];
            __stcg(&g_BF[i0 + tid], r_bt2 / (1.0f + a));
        }
        grid_sync(tgt += NB);

        // AF = AT / (1 + K @ BF) -- groups 0..3 read SMEM-resident half, 4..7 read L2
        load_vec_h(s_vh, g_BF, tid);
        __syncthreads();
        {
            float acc[4] = {0.f, 0.f, 0.f, 0.f};
            const uint4* vh4 = (const uint4*)((const char*)s_vh + (q << 11));
            if (g < 4) {
                const unsigned char* Mp = s_pref + (size_t)(g << 2) * N + (q << 10);
                dot8_body(Mp, false, vh4, lane, acc);
            } else {
                const unsigned char* Mp = g_K8 + (size_t)(i0 + (g << 2)) * N + (q << 10);
                dot8_body(Mp, true, vh4, lane, acc);
            }
            warp_reduce_part(acc, g << 2, q, lane, s_part);
        }
        __syncthreads();
        if (tid < RPB) {
            const float a = s_part[tid * 4] + s_part[tid * 4 + 1]
                          + s_part[tid * 4 + 2] + s_part[tid * 4 + 3];
            __stcg(&g_AF[i0 + tid], r_at / (1.0f + a));
        }
        grid_sync(tgt += NB);
    }

    // ---------- fp16 refinement iterations ----------
    for (int it = 0; it < NIT16; ++it) {
        load_vec_f(s_vec, g_AF, tid);
        __syncthreads();
        dot16(g_KhT, s_vec, i0, g, q, lane, s_part);
        __syncthreads();
        if (tid < RPB) {
            const float a = s_part[tid * 4] + s_part[tid * 4 + 1]
                          + s_part[tid * 4 + 2] + s_part[tid * 4 + 3];
            __stcg(&g_BF[i0 + tid], r_bt2 / (1.0f + a));
        }
        grid_sync(tgt += NB);

        load_vec_f(s_vec, g_BF, tid);
        __syncthreads();
        dot16(g_Kh, s_vec, i0, g, q, lane, s_part);
        __syncthreads();
        if (tid < RPB) {
            const float a = s_part[tid * 4] + s_part[tid * 4 + 1]
                          + s_part[tid * 4 + 2] + s_part[tid * 4 + 3];
            const float af = r_at / (1.0f + a);
            if (it == NIT16 - 1) s_af[tid] = af;           // final: keep local
            else                 __stcg(&g_AF[i0 + tid], af);
        }
        if (it != NIT16 - 1) grid_sync(tgt += NB);
        else                 __syncthreads();
    }

    // ---------- output: C[i][j] = AF_i * k_ij^2 * BF_j  (fp32 k) ----------
    load_vec_f(s_vec, g_BF, tid);
    __syncthreads();

    const float af = s_af[w];                              // warp w -> row i0 + w
    const float4* sv4 = (const float4*)s_vec;
#pragma unroll 4
    for (int s = 0; s < 32; ++s) {
        const int j = s * 128 + lane * 4;
        const size_t off = (size_t)(i0 + w) * N + j;
        const float4 kv = __ldcs((const float4*)(k + off));
        const float4 bv = sv4[j >> 2];
        float4 c4;
        c4.x = af * kv.x * kv.x * bv.x;
        c4.y = af * kv.y * kv.y * bv.y;
        c4.z = af * kv.z * kv.z * bv.z;
        c4.w = af * kv.w * kv.w * bv.w;
        *(float4*)(C + off) = c4;
    }
}

extern "C" void kernel_launch(void* const* d_in, const int* in_sizes, int n_in,
                              void* d_out, int out_size) {
    const float* AT = (const float*)d_in[0];
    const float* k  = (const float*)d_in[1];
    const float* bt = (const float*)d_in[2];
    float* C = (float*)d_out;

    cudaFuncSetAttribute(competitive_kernel,
                         cudaFuncAttributeMaxDynamicSharedMemorySize, SMEM_DYN);
    reset_bar_kernel<<<1, 1>>>();
    competitive_kernel<<<NB, NT, SMEM_DYN>>>(AT, k, bt, C);
}